// round 1
// baseline (speedup 1.0000x reference)
#include <cuda_runtime.h>
#include <math.h>

// ---------------- scratch (device globals; no allocation) ----------------
__device__ float g_k1[16 * 512 * 200];   // key conv1 out
__device__ float g_k [16 *  80 * 200];   // key encoder out
__device__ float g_q1[16 * 160 * 800];   // query conv1 out
__device__ float g_q2[16 *  80 * 800];   // query conv2 out
__device__ float g_qf[16 *  80 * 800];   // query encoder out

// ---------------- conv k=3 pad=1 (+bias, optional ReLU) ------------------
// grid: (ceil(T/64), ceil(Cout/64), B), block 256
// thread tile: 4 co x 4 t.  smem: sx[CIN][68] (t0-1..t0+64), sw[16ci][3][64co]
template<int CIN, bool RELU>
__global__ void conv3_kernel(const float* __restrict__ x, const float* __restrict__ w,
                             const float* __restrict__ bias, float* __restrict__ y,
                             int T, int Cout)
{
    extern __shared__ float smem[];
    float* sx = smem;                    // CIN * 68
    float* sw = smem + CIN * 68;         // 16*3*64 = 3072

    const int t0  = blockIdx.x * 64;
    const int co0 = blockIdx.y * 64;
    const int b   = blockIdx.z;
    const int tid = threadIdx.x;

    // load input tile (with halo, zero-padded)
    for (int idx = tid; idx < CIN * 66; idx += 256) {
        int ci = idx / 66, j = idx - ci * 66;
        int t = t0 + j - 1;
        sx[ci * 68 + j] = (t >= 0 && t < T) ? x[((size_t)b * CIN + ci) * T + t] : 0.f;
    }

    const int tt = (tid & 15) << 2;   // t offset within tile (0..60)
    const int ct = (tid >> 4) << 2;   // co offset within tile (0..60)
    float acc[4][4] = {};

    for (int ci0 = 0; ci0 < CIN; ci0 += 16) {
        __syncthreads();
        // stage 16 ci x 3 k x 64 co weights
        for (int idx = tid; idx < 3072; idx += 256) {
            int col = idx / 48;
            int rem = idx - col * 48;
            int cc = rem / 3, dk = rem - cc * 3;
            int co = co0 + col;
            sw[(cc * 3 + dk) * 64 + col] =
                (co < Cout) ? w[((size_t)co * CIN + ci0 + cc) * 3 + dk] : 0.f;
        }
        __syncthreads();
        #pragma unroll
        for (int cc = 0; cc < 16; cc++) {
            const float* xr = &sx[(size_t)(ci0 + cc) * 68 + tt];
            float xv[6];
            #pragma unroll
            for (int j = 0; j < 6; j++) xv[j] = xr[j];
            #pragma unroll
            for (int r = 0; r < 4; r++) {
                const float* wr = &sw[cc * 192 + ct + r];
                float w0 = wr[0], w1 = wr[64], w2 = wr[128];
                #pragma unroll
                for (int u = 0; u < 4; u++)
                    acc[r][u] = fmaf(w0, xv[u], fmaf(w1, xv[u+1], fmaf(w2, xv[u+2], acc[r][u])));
            }
        }
    }

    #pragma unroll
    for (int r = 0; r < 4; r++) {
        int co = co0 + ct + r;
        if (co < Cout) {
            float bv = bias[co];
            #pragma unroll
            for (int u = 0; u < 4; u++) {
                int t = t0 + tt + u;
                if (t < T) {
                    float v = acc[r][u] + bv;
                    if (RELU) v = fmaxf(v, 0.f);
                    y[((size_t)b * Cout + co) * T + t] = v;
                }
            }
        }
    }
}

// ---------------- 1x1 conv, Cout = 80 fixed (+bias, optional ReLU) -------
// grid: (ceil(T/128), B), block 256.  thread tile: 10 co x 4 t (float4 x reads)
template<int CIN, bool RELU>
__global__ void conv1x1_kernel(const float* __restrict__ x, const float* __restrict__ w,
                               const float* __restrict__ bias, float* __restrict__ y, int T)
{
    __shared__ float sx[32 * 128];
    __shared__ float sw[32 * 80];
    const int t0  = blockIdx.x * 128;
    const int b   = blockIdx.y;
    const int tid = threadIdx.x;
    const int tt  = (tid & 31) << 2;       // t offset (0..124)
    const int cg  = (tid >> 5) * 10;       // co base (0..70)
    float acc[10][4] = {};

    for (int ci0 = 0; ci0 < CIN; ci0 += 32) {
        __syncthreads();
        for (int idx = tid; idx < 4096; idx += 256) {
            int cc = idx >> 7, j = idx & 127;
            int ci = ci0 + cc, t = t0 + j;
            sx[idx] = (ci < CIN && t < T) ? x[((size_t)b * CIN + ci) * T + t] : 0.f;
        }
        for (int idx = tid; idx < 2560; idx += 256) {
            int co = idx >> 5, cc = idx & 31;
            int ci = ci0 + cc;
            sw[cc * 80 + co] = (ci < CIN) ? w[(size_t)co * CIN + ci] : 0.f;
        }
        __syncthreads();
        #pragma unroll 8
        for (int cc = 0; cc < 32; cc++) {
            float4 xv = *(const float4*)&sx[cc * 128 + tt];
            #pragma unroll
            for (int r = 0; r < 10; r++) {
                float wv = sw[cc * 80 + cg + r];
                acc[r][0] = fmaf(wv, xv.x, acc[r][0]);
                acc[r][1] = fmaf(wv, xv.y, acc[r][1]);
                acc[r][2] = fmaf(wv, xv.z, acc[r][2]);
                acc[r][3] = fmaf(wv, xv.w, acc[r][3]);
            }
        }
    }

    #pragma unroll
    for (int r = 0; r < 10; r++) {
        int co = cg + r;
        float bv = bias[co];
        #pragma unroll
        for (int u = 0; u < 4; u++) {
            int t = t0 + tt + u;
            if (t < T) {
                float v = acc[r][u] + bv;
                if (RELU) v = fmaxf(v, 0.f);
                y[((size_t)b * 80 + co) * T + t] = v;
            }
        }
    }
}

// ---------------- fused L2-dist + log_softmax + log(prior) ---------------
// grid: (T1/16 = 50, B), block 256
// smem: sk[80][200] + sq[80][16] + sq2[16] + sd[16][200]  = ~82 KB
__global__ void attention_kernel(const float* __restrict__ q, const float* __restrict__ k,
                                 const float* __restrict__ prior, float* __restrict__ out)
{
    extern __shared__ float smem[];
    float* sk  = smem;                  // 80*200
    float* sq  = sk + 80 * 200;         // 80*16
    float* sq2 = sq + 80 * 16;          // 16
    float* sd  = sq2 + 16;              // 16*200

    const int b    = blockIdx.y;
    const int t1_0 = blockIdx.x * 16;
    const int tid  = threadIdx.x;

    for (int idx = tid; idx < 80 * 200; idx += 256)
        sk[idx] = k[(size_t)b * 16000 + idx];
    for (int idx = tid; idx < 80 * 16; idx += 256) {
        int c = idx >> 4, j = idx & 15;
        sq[idx] = q[((size_t)b * 80 + c) * 800 + t1_0 + j];
    }
    __syncthreads();

    if (tid < 16) {                      // ||q||^2 per t1
        float s = 0.f;
        #pragma unroll 8
        for (int c = 0; c < 80; c++) { float v = sq[c * 16 + tid]; s = fmaf(v, v, s); }
        sq2[tid] = s;
    }
    __syncthreads();

    if (tid < 200) {                     // one s-column per thread
        float acc[16] = {};
        float k2 = 0.f;
        #pragma unroll 4
        for (int c = 0; c < 80; c++) {
            float kc = sk[c * 200 + tid];
            k2 = fmaf(kc, kc, k2);
            #pragma unroll
            for (int jj = 0; jj < 4; jj++) {
                float4 qv = *(const float4*)&sq[c * 16 + jj * 4];
                acc[jj*4+0] = fmaf(kc, qv.x, acc[jj*4+0]);
                acc[jj*4+1] = fmaf(kc, qv.y, acc[jj*4+1]);
                acc[jj*4+2] = fmaf(kc, qv.z, acc[jj*4+2]);
                acc[jj*4+3] = fmaf(kc, qv.w, acc[jj*4+3]);
            }
        }
        #pragma unroll
        for (int j = 0; j < 16; j++)
            sd[j * 200 + tid] = -0.0005f * (sq2[j] + k2 - 2.f * acc[j]);
    }
    __syncthreads();

    const int warp = tid >> 5, lane = tid & 31;
    for (int j = warp; j < 16; j += 8) {
        float m = -1e30f;
        for (int s = lane; s < 200; s += 32) m = fmaxf(m, sd[j * 200 + s]);
        #pragma unroll
        for (int o = 16; o; o >>= 1) m = fmaxf(m, __shfl_xor_sync(0xffffffffu, m, o));
        float sum = 0.f;
        for (int s = lane; s < 200; s += 32) sum += expf(sd[j * 200 + s] - m);
        #pragma unroll
        for (int o = 16; o; o >>= 1) sum += __shfl_xor_sync(0xffffffffu, sum, o);
        float lse = m + logf(sum);
        const float* pr = &prior[((size_t)b * 800 + t1_0 + j) * 200];
        float*       op = &out  [((size_t)b * 800 + t1_0 + j) * 200];
        for (int s = lane; s < 200; s += 32)
            op[s] = sd[j * 200 + s] - lse + logf(pr[s] + 1e-8f);
    }
}

// -------------------------------- launch ---------------------------------
extern "C" void kernel_launch(void* const* d_in, const int* in_sizes, int n_in,
                              void* d_out, int out_size)
{
    const float* queries = (const float*)d_in[0];   // (16,80,800)
    const float* keys    = (const float*)d_in[1];   // (16,256,200)
    const float* prior   = (const float*)d_in[2];   // (16,800,200)
    const float* kw1 = (const float*)d_in[3];
    const float* kb1 = (const float*)d_in[4];
    const float* kw2 = (const float*)d_in[5];
    const float* kb2 = (const float*)d_in[6];
    const float* qw1 = (const float*)d_in[7];
    const float* qb1 = (const float*)d_in[8];
    const float* qw2 = (const float*)d_in[9];
    const float* qb2 = (const float*)d_in[10];
    const float* qw3 = (const float*)d_in[11];
    const float* qb3 = (const float*)d_in[12];
    float* out = (float*)d_out;                      // (16,1,800,200)

    float *k1buf, *kbuf, *q1buf, *q2buf, *qbuf;
    cudaGetSymbolAddress((void**)&k1buf, g_k1);
    cudaGetSymbolAddress((void**)&kbuf,  g_k);
    cudaGetSymbolAddress((void**)&q1buf, g_q1);
    cudaGetSymbolAddress((void**)&q2buf, g_q2);
    cudaGetSymbolAddress((void**)&qbuf,  g_qf);

    const int smem_k1   = (256 * 68 + 3072) * 4;    // 81920
    const int smem_q1   = (80  * 68 + 3072) * 4;    // 34048
    const int smem_attn = (80*200 + 80*16 + 16 + 16*200) * 4;  // 81984

    cudaFuncSetAttribute((const void*)conv3_kernel<256, true>,
                         cudaFuncAttributeMaxDynamicSharedMemorySize, smem_k1);
    cudaFuncSetAttribute((const void*)attention_kernel,
                         cudaFuncAttributeMaxDynamicSharedMemorySize, smem_attn);

    // key encoder
    conv3_kernel<256, true><<<dim3(4, 8, 16), 256, smem_k1>>>(keys, kw1, kb1, k1buf, 200, 512);
    conv1x1_kernel<512, false><<<dim3(2, 16), 256>>>(k1buf, kw2, kb2, kbuf, 200);
    // query encoder
    conv3_kernel<80, true><<<dim3(13, 3, 16), 256, smem_q1>>>(queries, qw1, qb1, q1buf, 800, 160);
    conv1x1_kernel<160, true><<<dim3(7, 16), 256>>>(q1buf, qw2, qb2, q2buf, 800);
    conv1x1_kernel<80, false><<<dim3(7, 16), 256>>>(q2buf, qw3, qb3, qbuf, 800);
    // fused distance + log_softmax + prior
    attention_kernel<<<dim3(50, 16), 256, smem_attn>>>(qbuf, kbuf, prior, out);
}

// round 2
// speedup vs baseline: 1.1322x; 1.1322x over previous
#include <cuda_runtime.h>
#include <math.h>

// ---------------- scratch (device globals; no allocation) ----------------
__device__ float g_k1[16 * 512 * 200];   // key conv1 out
__device__ float g_k [16 *  80 * 200];   // key encoder out
__device__ float g_q1[16 * 160 * 800];   // query conv1 out
__device__ float g_qf[16 *  80 * 800];   // query encoder out

// ---------------- packed fp32x2 FMA (Blackwell) ---------------------------
__device__ __forceinline__ float2 ffma2(float2 a, float2 b, float2 c) {
    unsigned long long ua = *reinterpret_cast<unsigned long long*>(&a);
    unsigned long long ub = *reinterpret_cast<unsigned long long*>(&b);
    unsigned long long uc = *reinterpret_cast<unsigned long long*>(&c);
    unsigned long long ud;
    asm("fma.rn.f32x2 %0, %1, %2, %3;" : "=l"(ud) : "l"(ua), "l"(ub), "l"(uc));
    return *reinterpret_cast<float2*>(&ud);
}

// =================== STAGE A: both k=3 pad=1 convs, one launch ============
// block tile 64co x 64t, 256 threads, thread 4co x 4t, ci chunks of 16.
// smem: sx[CIN][68] + sw2[16*3*64] float2 (weights pre-duplicated (w,w)).
__device__ __forceinline__ void conv3_body(
    const float* __restrict__ x, const float* __restrict__ w,
    const float* __restrict__ bias, float* __restrict__ y,
    int CIN, int Cout, int T, int b, int t_tile, int co_tile, float* smem)
{
    float*  sx  = smem;                            // CIN * 68
    float2* sw2 = (float2*)(smem + CIN * 68);      // 16*3*64 pairs

    const int t0  = t_tile * 64;
    const int co0 = co_tile * 64;
    const int tid = threadIdx.x;

    // input tile with halo, zero-padded
    for (int idx = tid; idx < CIN * 66; idx += 256) {
        int ci = idx / 66, j = idx - ci * 66;
        int t = t0 + j - 1;
        sx[ci * 68 + j] = (t >= 0 && t < T) ? x[((size_t)b * CIN + ci) * T + t] : 0.f;
    }

    const int tt = (tid & 15) << 2;   // t offset 0..60 (even)
    const int ct = (tid >> 4) << 2;   // co offset 0..60 (even)
    float2 acc01[4] = {}, acc23[4] = {};

    for (int ci0 = 0; ci0 < CIN; ci0 += 16) {
        __syncthreads();
        // stage 16ci x 3k x 64co duplicated weights
        for (int idx = tid; idx < 3072; idx += 256) {
            int col = idx / 48;
            int rem = idx - col * 48;
            int cc = rem / 3, dk = rem - cc * 3;
            int co = co0 + col;
            float wv = (co < Cout) ? w[((size_t)co * CIN + ci0 + cc) * 3 + dk] : 0.f;
            sw2[(cc * 3 + dk) * 64 + col] = make_float2(wv, wv);
        }
        __syncthreads();
        #pragma unroll
        for (int cc = 0; cc < 16; cc++) {
            const float2* xr = (const float2*)&sx[(ci0 + cc) * 68 + tt];
            float2 A = xr[0], C = xr[1], E = xr[2];
            float2 Bp = make_float2(A.y, C.x);
            float2 Dp = make_float2(C.y, E.x);
            const float4* wq = (const float4*)&sw2[(cc * 3) * 64 + ct];
            float4 t0a = wq[0],  t0b = wq[1];     // tap0, r=0..3
            float4 t1a = wq[32], t1b = wq[33];    // tap1 (+64 float2)
            float4 t2a = wq[64], t2b = wq[65];    // tap2 (+128 float2)
            float2 w0[4] = { {t0a.x,t0a.y},{t0a.z,t0a.w},{t0b.x,t0b.y},{t0b.z,t0b.w} };
            float2 w1[4] = { {t1a.x,t1a.y},{t1a.z,t1a.w},{t1b.x,t1b.y},{t1b.z,t1b.w} };
            float2 w2[4] = { {t2a.x,t2a.y},{t2a.z,t2a.w},{t2b.x,t2b.y},{t2b.z,t2b.w} };
            #pragma unroll
            for (int r = 0; r < 4; r++) {
                acc01[r] = ffma2(w0[r], A, ffma2(w1[r], Bp, ffma2(w2[r], C, acc01[r])));
                acc23[r] = ffma2(w0[r], C, ffma2(w1[r], Dp, ffma2(w2[r], E, acc23[r])));
            }
        }
    }

    #pragma unroll
    for (int r = 0; r < 4; r++) {
        int co = co0 + ct + r;
        if (co < Cout) {
            float bv = bias[co];
            float v[4] = { acc01[r].x, acc01[r].y, acc23[r].x, acc23[r].y };
            #pragma unroll
            for (int u = 0; u < 4; u++) {
                int t = t0 + tt + u;
                if (t < T)
                    y[((size_t)b * Cout + co) * T + t] = fmaxf(v[u] + bv, 0.f);
            }
        }
    }
}

__global__ void stageA_kernel(
    const float* __restrict__ keys, const float* __restrict__ kw1, const float* __restrict__ kb1,
    const float* __restrict__ queries, const float* __restrict__ qw1, const float* __restrict__ qb1,
    float* __restrict__ k1out, float* __restrict__ q1out)
{
    extern __shared__ float smem[];
    int id = blockIdx.x;
    if (id < 512) {
        int b = id >> 5, r = id & 31;
        conv3_body(keys, kw1, kb1, k1out, 256, 512, 200, b, r & 3, r >> 2, smem);
    } else {
        id -= 512;
        int b = id / 39, r = id - b * 39;
        conv3_body(queries, qw1, qb1, q1out, 80, 160, 800, b, r % 13, r / 13, smem);
    }
}

// =================== STAGE B: key 1x1 + query 1x1 chain, one launch =======
// common 1x1 accumulate: block 80co x 64t, 256 threads, thread 5co x 4t.
// sx[32][64], sw2[32*80] float2 duplicated.
__device__ __forceinline__ void acc1x1_chunk(
    const float* sx, const float2* sw2, int tt, int cg, int CC,
    float2 a0[5], float2 a1[5])
{
    #pragma unroll 4
    for (int cc = 0; cc < CC; cc++) {
        float4 xv = *(const float4*)&sx[cc * 64 + tt];
        float2 x01 = make_float2(xv.x, xv.y);
        float2 x23 = make_float2(xv.z, xv.w);
        #pragma unroll
        for (int r = 0; r < 5; r++) {
            float2 wd = sw2[cc * 80 + cg + r];
            a0[r] = ffma2(wd, x01, a0[r]);
            a1[r] = ffma2(wd, x23, a1[r]);
        }
    }
}

__device__ __forceinline__ void key1x1_body(
    const float* __restrict__ x, const float* __restrict__ w,
    const float* __restrict__ bias, float* __restrict__ y, int bx, float* smem)
{
    float*  sx  = smem;                  // 32*64
    float2* sw2 = (float2*)(smem + 2048);
    const int t0 = (bx & 3) * 64;
    const int b  = bx >> 2;
    const int tid = threadIdx.x;
    const int tt = (tid & 15) << 2;
    const int cg = (tid >> 4) * 5;
    float2 a0[5] = {}, a1[5] = {};

    for (int ci0 = 0; ci0 < 512; ci0 += 32) {
        __syncthreads();
        for (int idx = tid; idx < 2048; idx += 256) {
            int cc = idx >> 6, j = idx & 63;
            int t = t0 + j;
            sx[idx] = (t < 200) ? x[((size_t)(b * 512) + ci0 + cc) * 200 + t] : 0.f;
        }
        for (int idx = tid; idx < 2560; idx += 256) {
            int cc = idx / 80, co = idx - cc * 80;
            float wv = w[(size_t)co * 512 + ci0 + cc];
            sw2[idx] = make_float2(wv, wv);
        }
        __syncthreads();
        acc1x1_chunk(sx, sw2, tt, cg, 32, a0, a1);
    }
    #pragma unroll
    for (int r = 0; r < 5; r++) {
        int co = cg + r;
        float bv = bias[co];
        float v[4] = { a0[r].x, a0[r].y, a1[r].x, a1[r].y };
        #pragma unroll
        for (int u = 0; u < 4; u++) {
            int t = t0 + tt + u;
            if (t < 200)
                y[((size_t)(b * 80) + co) * 200 + t] = v[u] + bv;
        }
    }
}

__device__ __forceinline__ void qchain_body(
    const float* __restrict__ x, const float* __restrict__ w2, const float* __restrict__ b2,
    const float* __restrict__ w3, const float* __restrict__ b3,
    float* __restrict__ y, int bx, float* smem)
{
    float*  sx  = smem;                       // 32*64
    float2* sw2 = (float2*)(smem + 2048);     // 32*80 pairs (floats 2048..7167)
    float*  sh2 = smem + 7168;                // 80*64
    const int b  = bx / 13;
    const int t0 = (bx - b * 13) * 64;
    const int tid = threadIdx.x;
    const int tt = (tid & 15) << 2;
    const int cg = (tid >> 4) * 5;

    // phase 1: h2 = relu(W2 x + b2), CIN=160
    float2 a0[5] = {}, a1[5] = {};
    for (int ci0 = 0; ci0 < 160; ci0 += 32) {
        __syncthreads();
        for (int idx = tid; idx < 2048; idx += 256) {
            int cc = idx >> 6, j = idx & 63;
            int t = t0 + j;
            sx[idx] = (t < 800) ? x[((size_t)(b * 160) + ci0 + cc) * 800 + t] : 0.f;
        }
        for (int idx = tid; idx < 2560; idx += 256) {
            int cc = idx / 80, co = idx - cc * 80;
            float wv = w2[(size_t)co * 160 + ci0 + cc];
            sw2[idx] = make_float2(wv, wv);
        }
        __syncthreads();
        acc1x1_chunk(sx, sw2, tt, cg, 32, a0, a1);
    }
    #pragma unroll
    for (int r = 0; r < 5; r++) {
        int co = cg + r;
        float bv = b2[co];
        sh2[co * 64 + tt + 0] = fmaxf(a0[r].x + bv, 0.f);
        sh2[co * 64 + tt + 1] = fmaxf(a0[r].y + bv, 0.f);
        sh2[co * 64 + tt + 2] = fmaxf(a1[r].x + bv, 0.f);
        sh2[co * 64 + tt + 3] = fmaxf(a1[r].y + bv, 0.f);
    }

    // phase 2: q = W3 h2 + b3, CIN=80 (h2 already in smem)
    float2 c0[5] = {}, c1[5] = {};
    for (int ci0 = 0; ci0 < 80; ci0 += 32) {
        int CC = min(32, 80 - ci0);
        __syncthreads();
        for (int idx = tid; idx < CC * 80; idx += 256) {
            int cc = idx / 80, co = idx - cc * 80;
            float wv = w3[(size_t)co * 80 + ci0 + cc];
            sw2[cc * 80 + co] = make_float2(wv, wv);
        }
        __syncthreads();
        acc1x1_chunk(sh2 + ci0 * 64, sw2, tt, cg, CC, c0, c1);
    }
    #pragma unroll
    for (int r = 0; r < 5; r++) {
        int co = cg + r;
        float bv = b3[co];
        float v[4] = { c0[r].x, c0[r].y, c1[r].x, c1[r].y };
        #pragma unroll
        for (int u = 0; u < 4; u++) {
            int t = t0 + tt + u;
            if (t < 800)
                y[((size_t)(b * 80) + co) * 800 + t] = v[u] + bv;
        }
    }
}

__global__ void stageB_kernel(
    const float* __restrict__ k1in, const float* __restrict__ kw2, const float* __restrict__ kb2,
    float* __restrict__ kout,
    const float* __restrict__ q1in, const float* __restrict__ qw2, const float* __restrict__ qb2,
    const float* __restrict__ qw3, const float* __restrict__ qb3, float* __restrict__ qout)
{
    extern __shared__ float smem[];
    int id = blockIdx.x;
    if (id < 64) key1x1_body(k1in, kw2, kb2, kout, id, smem);
    else         qchain_body(q1in, qw2, qb2, qw3, qb3, qout, id - 64, smem);
}

// =================== STAGE C: L2-dist + log_softmax + log(prior) ==========
// grid (25, 16), block 256, t1 tile 32.
// smem: sk[80][200] + sq[80][32] + sq2[32] + sd[32][200]  (99968 B)
__global__ void attention_kernel(const float* __restrict__ q, const float* __restrict__ k,
                                 const float* __restrict__ prior, float* __restrict__ out)
{
    extern __shared__ float smem[];
    float* sk  = smem;                  // 80*200
    float* sq  = sk + 16000;            // 80*32
    float* sq2 = sq + 2560;             // 32
    float* sd  = sq2 + 32;              // 32*200

    const int b    = blockIdx.y;
    const int t1_0 = blockIdx.x * 32;
    const int tid  = threadIdx.x;

    for (int idx = tid; idx < 16000; idx += 256)
        sk[idx] = k[(size_t)b * 16000 + idx];
    for (int idx = tid; idx < 2560; idx += 256) {
        int c = idx >> 5, j = idx & 31;
        sq[idx] = q[((size_t)b * 80 + c) * 800 + t1_0 + j];
    }
    __syncthreads();

    if (tid < 32) {                      // ||q||^2 per t1 row
        float s = 0.f;
        #pragma unroll 8
        for (int c = 0; c < 80; c++) { float v = sq[c * 32 + tid]; s = fmaf(v, v, s); }
        sq2[tid] = s;
    }
    __syncthreads();

    if (tid < 200) {                     // one s-column per thread, 32 rows
        float2 acc[16] = {};
        float k2 = 0.f;
        #pragma unroll 4
        for (int c = 0; c < 80; c++) {
            float kc = sk[c * 200 + tid];
            float2 kd = make_float2(kc, kc);
            k2 = fmaf(kc, kc, k2);
            const float4* qr = (const float4*)&sq[c * 32];
            #pragma unroll
            for (int jj = 0; jj < 8; jj++) {
                float4 qv = qr[jj];
                acc[2*jj]   = ffma2(kd, make_float2(qv.x, qv.y), acc[2*jj]);
                acc[2*jj+1] = ffma2(kd, make_float2(qv.z, qv.w), acc[2*jj+1]);
            }
        }
        #pragma unroll
        for (int p = 0; p < 16; p++) {
            int j = 2 * p;
            sd[j * 200 + tid]       = -0.0005f * (sq2[j]     + k2 - 2.f * acc[p].x);
            sd[(j + 1) * 200 + tid] = -0.0005f * (sq2[j + 1] + k2 - 2.f * acc[p].y);
        }
    }
    __syncthreads();

    const int warp = tid >> 5, lane = tid & 31;
    for (int j = warp; j < 32; j += 8) {
        float m = -1e30f;
        for (int s = lane; s < 200; s += 32) m = fmaxf(m, sd[j * 200 + s]);
        #pragma unroll
        for (int o = 16; o; o >>= 1) m = fmaxf(m, __shfl_xor_sync(0xffffffffu, m, o));
        float sum = 0.f;
        for (int s = lane; s < 200; s += 32) sum += expf(sd[j * 200 + s] - m);
        #pragma unroll
        for (int o = 16; o; o >>= 1) sum += __shfl_xor_sync(0xffffffffu, sum, o);
        float lse = m + logf(sum);
        const float* pr = &prior[((size_t)b * 800 + t1_0 + j) * 200];
        float*       op = &out  [((size_t)b * 800 + t1_0 + j) * 200];
        for (int s = lane; s < 200; s += 32)
            op[s] = sd[j * 200 + s] - lse + logf(pr[s] + 1e-8f);
    }
}

// -------------------------------- launch ---------------------------------
extern "C" void kernel_launch(void* const* d_in, const int* in_sizes, int n_in,
                              void* d_out, int out_size)
{
    const float* queries = (const float*)d_in[0];   // (16,80,800)
    const float* keys    = (const float*)d_in[1];   // (16,256,200)
    const float* prior   = (const float*)d_in[2];   // (16,800,200)
    const float* kw1 = (const float*)d_in[3];
    const float* kb1 = (const float*)d_in[4];
    const float* kw2 = (const float*)d_in[5];
    const float* kb2 = (const float*)d_in[6];
    const float* qw1 = (const float*)d_in[7];
    const float* qb1 = (const float*)d_in[8];
    const float* qw2 = (const float*)d_in[9];
    const float* qb2 = (const float*)d_in[10];
    const float* qw3 = (const float*)d_in[11];
    const float* qb3 = (const float*)d_in[12];
    float* out = (float*)d_out;                      // (16,1,800,200)

    float *k1buf, *kbuf, *q1buf, *qbuf;
    cudaGetSymbolAddress((void**)&k1buf, g_k1);
    cudaGetSymbolAddress((void**)&kbuf,  g_k);
    cudaGetSymbolAddress((void**)&q1buf, g_q1);
    cudaGetSymbolAddress((void**)&qbuf,  g_qf);

    const int smem_A    = 256 * 68 * 4 + 3072 * 8;               // 94208
    const int smem_B    = (2048 + 5120 + 5120) * 4;              // 49152
    const int smem_attn = (16000 + 2560 + 32 + 6400) * 4;        // 99968

    cudaFuncSetAttribute((const void*)stageA_kernel,
                         cudaFuncAttributeMaxDynamicSharedMemorySize, smem_A);
    cudaFuncSetAttribute((const void*)stageB_kernel,
                         cudaFuncAttributeMaxDynamicSharedMemorySize, smem_B);
    cudaFuncSetAttribute((const void*)attention_kernel,
                         cudaFuncAttributeMaxDynamicSharedMemorySize, smem_attn);

    stageA_kernel<<<1136, 256, smem_A>>>(keys, kw1, kb1, queries, qw1, qb1, k1buf, q1buf);
    stageB_kernel<<<272, 256, smem_B>>>(k1buf, kw2, kb2, kbuf, q1buf, qw2, qb2, qw3, qb3, qbuf);
    attention_kernel<<<dim3(25, 16), 256, smem_attn>>>(qbuf, kbuf, prior, out);
}

// round 4
// speedup vs baseline: 1.7260x; 1.5244x over previous
#include <cuda_runtime.h>
#include <math.h>

// ---------------- scratch (device globals; no allocation) ----------------
__device__ float g_k1  [16 * 512 * 200];   // key conv1 out
__device__ float g_k   [16 *  80 * 200];   // key encoder out
__device__ float g_q1  [16 * 160 * 800];   // query conv1 out
__device__ float g_qf  [16 *  80 * 800];   // query encoder out
__device__ float g_kw1T[768 * 512];        // kw1 transposed [(ci*3+k)][co]
__device__ float g_qw1T[240 * 160];
__device__ float g_kw2T[512 *  80];        // kw2 transposed [ci][co]
__device__ float g_qw2T[160 *  80];
__device__ float g_qw3T[ 80 *  80];

// ---------------- packed fp32x2 FMA (Blackwell) ---------------------------
__device__ __forceinline__ float2 ffma2(float2 a, float2 b, float2 c) {
    unsigned long long ua = *reinterpret_cast<unsigned long long*>(&a);
    unsigned long long ub = *reinterpret_cast<unsigned long long*>(&b);
    unsigned long long uc = *reinterpret_cast<unsigned long long*>(&c);
    unsigned long long ud;
    asm("fma.rn.f32x2 %0, %1, %2, %3;" : "=l"(ud) : "l"(ua), "l"(ub), "l"(uc));
    return *reinterpret_cast<float2*>(&ud);
}
__device__ __forceinline__ float2 dup(float v) { return make_float2(v, v); }

// =================== PREP: transpose all weights ==========================
// kw1T[(ci*3+k)*512+co], qw1T[(ci*3+k)*160+co], kw2T[ci*80+co], qw2T, qw3T
__global__ void prep_kernel(const float* __restrict__ kw1, const float* __restrict__ qw1,
                            const float* __restrict__ kw2, const float* __restrict__ qw2,
                            const float* __restrict__ qw3,
                            float* __restrict__ kw1T, float* __restrict__ qw1T,
                            float* __restrict__ kw2T, float* __restrict__ qw2T,
                            float* __restrict__ qw3T)
{
    int i = blockIdx.x * 256 + threadIdx.x;
    if (i < 393216) {                    // kw1: (512,256,3)
        int r = i >> 9, co = i & 511;
        int ci = r / 3, k = r - ci * 3;
        kw1T[i] = kw1[(co * 256 + ci) * 3 + k];
        return;
    }
    i -= 393216;
    if (i < 38400) {                     // qw1: (160,80,3)
        int r = i / 160, co = i - r * 160;
        int ci = r / 3, k = r - ci * 3;
        qw1T[i] = qw1[(co * 80 + ci) * 3 + k];
        return;
    }
    i -= 38400;
    if (i < 40960) {                     // kw2: (80,512,1)
        int ci = i / 80, co = i - ci * 80;
        kw2T[i] = kw2[co * 512 + ci];
        return;
    }
    i -= 40960;
    if (i < 12800) {                     // qw2: (80,160,1)
        int ci = i / 80, co = i - ci * 80;
        qw2T[i] = qw2[co * 160 + ci];
        return;
    }
    i -= 12800;
    if (i < 6400) {                      // qw3: (80,80,1)
        int ci = i / 80, co = i - ci * 80;
        qw3T[i] = qw3[co * 80 + ci];
    }
}

// =================== STAGE A: both k=3 pad=1 convs ========================
// 256 threads = 16 cg x 16 tg; thread tile = (2*CPAIRS) co x 4 t (co-paired f32x2).
// block tile = 32*CPAIRS co x 64 t.  ci chunks of 32.
// smem: sx[32][68] + sw[32*3][COT]   (wT layout makes staging coalesced+conflict-free)
template<int CIN, int COUT, int TLEN, int CPAIRS>
__device__ __forceinline__ void conv3_body(
    const float* __restrict__ x, const float* __restrict__ wT,
    const float* __restrict__ bias, float* __restrict__ y,
    int b, int t_tile, int co_tile, float* smem)
{
    constexpr int COT = 32 * CPAIRS;
    float* sx = smem;               // 32*68
    float* sw = smem + 32 * 68;     // 32*3*COT

    const int tid = threadIdx.x;
    const int cg = tid & 15, tg = tid >> 4;
    const int tt = tg * 4, ct = cg * 2 * CPAIRS;
    const int t0 = t_tile * 64, co0 = co_tile * COT;
    const bool active = (t0 + tt) < TLEN;

    float2 acc[CPAIRS][4] = {};

    for (int ci0 = 0; ci0 < CIN; ci0 += 32) {
        const int CC = (CIN - ci0 < 32) ? (CIN - ci0) : 32;
        __syncthreads();
        for (int idx = tid; idx < CC * 66; idx += 256) {
            int cc = idx / 66, j = idx - cc * 66;
            int t = t0 + j - 1;
            sx[cc * 68 + j] = (t >= 0 && t < TLEN)
                ? x[((size_t)(b * CIN) + ci0 + cc) * TLEN + t] : 0.f;
        }
        for (int idx = tid; idx < CC * 3 * COT; idx += 256) {
            int r = idx / COT, co = idx - r * COT;
            sw[idx] = wT[(size_t)(ci0 * 3 + r) * COUT + co0 + co];
        }
        __syncthreads();
        if (active) {
            #pragma unroll 8
            for (int cc = 0; cc < CC; cc++) {
                const float* xr = &sx[cc * 68 + tt];
                float4 xa = *(const float4*)xr;
                float2 xb = *(const float2*)(xr + 4);
                float2 xv[6] = { dup(xa.x), dup(xa.y), dup(xa.z),
                                 dup(xa.w), dup(xb.x), dup(xb.y) };
                float2 wk[3][CPAIRS];
                #pragma unroll
                for (int k = 0; k < 3; k++) {
                    const float* wb = &sw[(cc * 3 + k) * COT + ct];
                    if constexpr ((CPAIRS & 1) == 0) {
                        #pragma unroll
                        for (int q = 0; q < CPAIRS / 2; q++) {
                            float4 wv = *(const float4*)(wb + 4 * q);
                            wk[k][2*q]   = make_float2(wv.x, wv.y);
                            wk[k][2*q+1] = make_float2(wv.z, wv.w);
                        }
                    } else {
                        #pragma unroll
                        for (int p = 0; p < CPAIRS; p++)
                            wk[k][p] = *(const float2*)(wb + 2 * p);
                    }
                }
                #pragma unroll
                for (int u = 0; u < 4; u++)
                    #pragma unroll
                    for (int p = 0; p < CPAIRS; p++)
                        acc[p][u] = ffma2(wk[0][p], xv[u],
                                    ffma2(wk[1][p], xv[u+1],
                                    ffma2(wk[2][p], xv[u+2], acc[p][u])));
            }
        }
    }

    if (active) {
        // raggedness aligns so full float4 stores are always in-bounds when active
        #pragma unroll
        for (int p = 0; p < CPAIRS; p++) {
            int co = co0 + ct + 2 * p;
            float2 bv = *(const float2*)&bias[co];
            float4 v0 = { fmaxf(acc[p][0].x + bv.x, 0.f), fmaxf(acc[p][1].x + bv.x, 0.f),
                          fmaxf(acc[p][2].x + bv.x, 0.f), fmaxf(acc[p][3].x + bv.x, 0.f) };
            float4 v1 = { fmaxf(acc[p][0].y + bv.y, 0.f), fmaxf(acc[p][1].y + bv.y, 0.f),
                          fmaxf(acc[p][2].y + bv.y, 0.f), fmaxf(acc[p][3].y + bv.y, 0.f) };
            *(float4*)&y[((size_t)(b * COUT) + co    ) * TLEN + t0 + tt] = v0;
            *(float4*)&y[((size_t)(b * COUT) + co + 1) * TLEN + t0 + tt] = v1;
        }
    }
}

__global__ void stageA_kernel(
    const float* __restrict__ keys, const float* __restrict__ kb1,
    const float* __restrict__ queries, const float* __restrict__ qb1,
    float* __restrict__ k1out, float* __restrict__ q1out)
{
    extern __shared__ float smem[];
    int id = blockIdx.x;
    if (id < 256) {
        int r = id & 15;
        conv3_body<256, 512, 200, 4>(keys, g_kw1T, kb1, k1out,
                                     id >> 4, r & 3, r >> 2, smem);
    } else {
        int j = id - 256;
        conv3_body<80, 160, 800, 5>(queries, g_qw1T, qb1, q1out,
                                    j / 13, j % 13, 0, smem);
    }
}

// =================== STAGE B: key 1x1 + query 1x1 chain ===================
// 256 threads = 8 cg x 32 tg; thread 10 co (5 pairs) x 4 t; block 80co x 128t.
__device__ __forceinline__ void fma1x1_chunk(
    const float* __restrict__ sx, const float* __restrict__ sw,
    int tt, int cb, int CC, float2 acc[5][4])
{
    #pragma unroll 8
    for (int cc = 0; cc < CC; cc++) {
        float4 xq = *(const float4*)&sx[cc * 128 + tt];
        float2 xv[4] = { dup(xq.x), dup(xq.y), dup(xq.z), dup(xq.w) };
        const float2* wp = (const float2*)&sw[cc * 80 + cb];
        #pragma unroll
        for (int p = 0; p < 5; p++) {
            float2 wd = wp[p];
            #pragma unroll
            for (int u = 0; u < 4; u++)
                acc[p][u] = ffma2(wd, xv[u], acc[p][u]);
        }
    }
}

__device__ __forceinline__ void key1x1_body(
    const float* __restrict__ x, const float* __restrict__ wT,
    const float* __restrict__ bias, float* __restrict__ y,
    int b, int t_tile, float* smem)
{
    float* sx = smem;          // 32*128
    float* sw = smem + 4096;   // 32*80
    const int tid = threadIdx.x;
    const int cg = tid & 7, tg = tid >> 3;
    const int tt = tg * 4, cb = cg * 10;
    const int t0 = t_tile * 128;
    const bool active = (t0 + tt) < 200;
    float2 acc[5][4] = {};

    for (int ci0 = 0; ci0 < 512; ci0 += 32) {
        __syncthreads();
        for (int idx = tid; idx < 4096; idx += 256) {
            int cc = idx >> 7, j = idx & 127;
            int t = t0 + j;
            sx[idx] = (t < 200) ? x[((size_t)(b * 512) + ci0 + cc) * 200 + t] : 0.f;
        }
        for (int idx = tid; idx < 2560; idx += 256)
            sw[idx] = wT[(size_t)ci0 * 80 + idx];
        __syncthreads();
        if (active) fma1x1_chunk(sx, sw, tt, cb, 32, acc);
    }
    if (active) {
        #pragma unroll
        for (int p = 0; p < 5; p++) {
            int co = cb + 2 * p;
            float2 bv = *(const float2*)&bias[co];
            float4 v0 = { acc[p][0].x + bv.x, acc[p][1].x + bv.x,
                          acc[p][2].x + bv.x, acc[p][3].x + bv.x };
            float4 v1 = { acc[p][0].y + bv.y, acc[p][1].y + bv.y,
                          acc[p][2].y + bv.y, acc[p][3].y + bv.y };
            *(float4*)&y[((size_t)(b * 80) + co    ) * 200 + t0 + tt] = v0;
            *(float4*)&y[((size_t)(b * 80) + co + 1) * 200 + t0 + tt] = v1;
        }
    }
}

__device__ __forceinline__ void qchain_body(
    const float* __restrict__ x, const float* __restrict__ w2T, const float* __restrict__ b2,
    const float* __restrict__ w3T, const float* __restrict__ b3,
    float* __restrict__ y, int b, int t_tile, float* smem)
{
    float* sx  = smem;          // 32*128
    float* sw  = smem + 4096;   // 32*80
    float* sh2 = smem + 6656;   // 80*128
    const int tid = threadIdx.x;
    const int cg = tid & 7, tg = tid >> 3;
    const int tt = tg * 4, cb = cg * 10;
    const int t0 = t_tile * 128;
    const bool active = (t0 + tt) < 800;

    {   // phase 1: h2 = relu(W2 x + b2), CIN=160 -> sh2
        float2 acc[5][4] = {};
        for (int ci0 = 0; ci0 < 160; ci0 += 32) {
            __syncthreads();
            for (int idx = tid; idx < 4096; idx += 256) {
                int cc = idx >> 7, j = idx & 127;
                int t = t0 + j;
                sx[idx] = (t < 800) ? x[((size_t)(b * 160) + ci0 + cc) * 800 + t] : 0.f;
            }
            for (int idx = tid; idx < 2560; idx += 256)
                sw[idx] = w2T[(size_t)ci0 * 80 + idx];
            __syncthreads();
            if (active) fma1x1_chunk(sx, sw, tt, cb, 32, acc);
        }
        if (active) {
            #pragma unroll
            for (int p = 0; p < 5; p++) {
                int co = cb + 2 * p;
                float2 bv = *(const float2*)&b2[co];
                float4 v0 = { fmaxf(acc[p][0].x + bv.x, 0.f), fmaxf(acc[p][1].x + bv.x, 0.f),
                              fmaxf(acc[p][2].x + bv.x, 0.f), fmaxf(acc[p][3].x + bv.x, 0.f) };
                float4 v1 = { fmaxf(acc[p][0].y + bv.y, 0.f), fmaxf(acc[p][1].y + bv.y, 0.f),
                              fmaxf(acc[p][2].y + bv.y, 0.f), fmaxf(acc[p][3].y + bv.y, 0.f) };
                *(float4*)&sh2[(co    ) * 128 + tt] = v0;
                *(float4*)&sh2[(co + 1) * 128 + tt] = v1;
            }
        }
    }
    {   // phase 2: q = W3 h2 + b3, CIN=80 (h2 in smem)
        float2 acc[5][4] = {};
        for (int ci0 = 0; ci0 < 80; ci0 += 32) {
            const int CC = (80 - ci0 < 32) ? (80 - ci0) : 32;
            __syncthreads();
            for (int idx = tid; idx < CC * 80; idx += 256)
                sw[idx] = w3T[(size_t)ci0 * 80 + idx];
            __syncthreads();
            if (active) fma1x1_chunk(&sh2[ci0 * 128], sw, tt, cb, CC, acc);
        }
        if (active) {
            #pragma unroll
            for (int p = 0; p < 5; p++) {
                int co = cb + 2 * p;
                float2 bv = *(const float2*)&b3[co];
                float4 v0 = { acc[p][0].x + bv.x, acc[p][1].x + bv.x,
                              acc[p][2].x + bv.x, acc[p][3].x + bv.x };
                float4 v1 = { acc[p][0].y + bv.y, acc[p][1].y + bv.y,
                              acc[p][2].y + bv.y, acc[p][3].y + bv.y };
                *(float4*)&y[((size_t)(b * 80) + co    ) * 800 + t0 + tt] = v0;
                *(float4*)&y[((size_t)(b * 80) + co + 1) * 800 + t0 + tt] = v1;
            }
        }
    }
}

__global__ void stageB_kernel(
    const float* __restrict__ k1in, const float* __restrict__ kb2, float* __restrict__ kout,
    const float* __restrict__ q1in, const float* __restrict__ qb2,
    const float* __restrict__ qb3, float* __restrict__ qout)
{
    extern __shared__ float smem[];
    int id = blockIdx.x;
    if (id < 32) key1x1_body(k1in, g_kw2T, kb2, kout, id >> 1, id & 1, smem);
    else {
        int j = id - 32;
        qchain_body(q1in, g_qw2T, qb2, g_qw3T, qb3, qout, j / 7, j % 7, smem);
    }
}

// =================== STAGE C: L2-dist + log_softmax + log(prior) ==========
__global__ void attention_kernel(const float* __restrict__ q, const float* __restrict__ k,
                                 const float* __restrict__ prior, float* __restrict__ out)
{
    extern __shared__ float smem[];
    float* sk  = smem;                  // 80*200
    float* sq  = sk + 16000;            // 80*32
    float* sq2 = sq + 2560;             // 32
    float* sd  = sq2 + 32;              // 32*200

    const int b    = blockIdx.y;
    const int t1_0 = blockIdx.x * 32;
    const int tid  = threadIdx.x;

    for (int idx = tid; idx < 16000; idx += 256)
        sk[idx] = k[(size_t)b * 16000 + idx];
    for (int idx = tid; idx < 2560; idx += 256) {
        int c = idx >> 5, j = idx & 31;
        sq[idx] = q[((size_t)b * 80 + c) * 800 + t1_0 + j];
    }
    __syncthreads();

    if (tid < 32) {
        float s = 0.f;
        #pragma unroll 8
        for (int c = 0; c < 80; c++) { float v = sq[c * 32 + tid]; s = fmaf(v, v, s); }
        sq2[tid] = s;
    }
    __syncthreads();

    if (tid < 200) {
        float2 acc[16] = {};
        float k2 = 0.f;
        #pragma unroll 4
        for (int c = 0; c < 80; c++) {
            float kc = sk[c * 200 + tid];
            float2 kd = make_float2(kc, kc);
            k2 = fmaf(kc, kc, k2);
            const float4* qr = (const float4*)&sq[c * 32];
            #pragma unroll
            for (int jj = 0; jj < 8; jj++) {
                float4 qv = qr[jj];
                acc[2*jj]   = ffma2(kd, make_float2(qv.x, qv.y), acc[2*jj]);
                acc[2*jj+1] = ffma2(kd, make_float2(qv.z, qv.w), acc[2*jj+1]);
            }
        }
        #pragma unroll
        for (int p = 0; p < 16; p++) {
            int j = 2 * p;
            sd[j * 200 + tid]       = -0.0005f * (sq2[j]     + k2 - 2.f * acc[p].x);
            sd[(j + 1) * 200 + tid] = -0.0005f * (sq2[j + 1] + k2 - 2.f * acc[p].y);
        }
    }
    __syncthreads();

    const int warp = tid >> 5, lane = tid & 31;
    for (int j = warp; j < 32; j += 8) {
        float m = -1e30f;
        for (int s = lane; s < 200; s += 32) m = fmaxf(m, sd[j * 200 + s]);
        #pragma unroll
        for (int o = 16; o; o >>= 1) m = fmaxf(m, __shfl_xor_sync(0xffffffffu, m, o));
        float sum = 0.f;
        for (int s = lane; s < 200; s += 32) sum += expf(sd[j * 200 + s] - m);
        #pragma unroll
        for (int o = 16; o; o >>= 1) sum += __shfl_xor_sync(0xffffffffu, sum, o);
        float lse = m + logf(sum);
        const float* pr = &prior[((size_t)b * 800 + t1_0 + j) * 200];
        float*       op = &out  [((size_t)b * 800 + t1_0 + j) * 200];
        for (int s = lane; s < 200; s += 32)
            op[s] = sd[j * 200 + s] - lse + logf(pr[s] + 1e-8f);
    }
}

// -------------------------------- launch ---------------------------------
extern "C" void kernel_launch(void* const* d_in, const int* in_sizes, int n_in,
                              void* d_out, int out_size)
{
    const float* queries = (const float*)d_in[0];
    const float* keys    = (const float*)d_in[1];
    const float* prior   = (const float*)d_in[2];
    const float* kw1 = (const float*)d_in[3];
    const float* kb1 = (const float*)d_in[4];
    const float* kw2 = (const float*)d_in[5];
    const float* kb2 = (const float*)d_in[6];
    const float* qw1 = (const float*)d_in[7];
    const float* qb1 = (const float*)d_in[8];
    const float* qw2 = (const float*)d_in[9];
    const float* qb2 = (const float*)d_in[10];
    const float* qw3 = (const float*)d_in[11];
    const float* qb3 = (const float*)d_in[12];
    float* out = (float*)d_out;

    float *k1buf, *kbuf, *q1buf, *qbuf;
    float *kw1T, *qw1T, *kw2T, *qw2T, *qw3T;
    cudaGetSymbolAddress((void**)&k1buf, g_k1);
    cudaGetSymbolAddress((void**)&kbuf,  g_k);
    cudaGetSymbolAddress((void**)&q1buf, g_q1);
    cudaGetSymbolAddress((void**)&qbuf,  g_qf);
    cudaGetSymbolAddress((void**)&kw1T, g_kw1T);
    cudaGetSymbolAddress((void**)&qw1T, g_qw1T);
    cudaGetSymbolAddress((void**)&kw2T, g_kw2T);
    cudaGetSymbolAddress((void**)&qw2T, g_qw2T);
    cudaGetSymbolAddress((void**)&qw3T, g_qw3T);

    const int smem_A    = (32 * 68 + 32 * 3 * 160) * 4;          // 70144
    const int smem_B    = (4096 + 2560 + 80 * 128) * 4;          // 67584
    const int smem_attn = (16000 + 2560 + 32 + 6400) * 4;        // 99968

    cudaFuncSetAttribute((const void*)stageA_kernel,
                         cudaFuncAttributeMaxDynamicSharedMemorySize, smem_A);
    cudaFuncSetAttribute((const void*)stageB_kernel,
                         cudaFuncAttributeMaxDynamicSharedMemorySize, smem_B);
    cudaFuncSetAttribute((const void*)attention_kernel,
                         cudaFuncAttributeMaxDynamicSharedMemorySize, smem_attn);

    prep_kernel<<<1921, 256>>>(kw1, qw1, kw2, qw2, qw3, kw1T, qw1T, kw2T, qw2T, qw3T);
    stageA_kernel<<<464, 256, smem_A>>>(keys, kb1, queries, qb1, k1buf, q1buf);
    stageB_kernel<<<144, 256, smem_B>>>(k1buf, kb2, kbuf, q1buf, qb2, qb3, qbuf);
    attention_kernel<<<dim3(25, 16), 256, smem_attn>>>(qbuf, kbuf, prior, out);
}